// round 9
// baseline (speedup 1.0000x reference)
#include <cuda_runtime.h>
#include <cuda_fp16.h>
#include <cstdint>

#define NBATCH 32
#define C 192
#define C3 576
#define T 256
#define V 25
#define TV 6400
#define S 3
#define MID 64

// fp16 scratch (device globals)
__device__ __half g_xTh [NBATCH * C  * TV];   // [n][c][v][t]
__device__ __half g_qkvh[NBATCH * C3 * TV];   // [n][d][v][t]
__device__ __half g_atth[NBATCH * S * T * T]; // [ns][q][t]
__device__ __half g_yh  [NBATCH * C  * TV];   // [n][ch][t][v]
__device__ __half g_winh[C3 * C];
__device__ __half g_wffh[C * C];

__device__ __forceinline__ void ldsm4(uint32_t& r0, uint32_t& r1, uint32_t& r2, uint32_t& r3, uint32_t a) {
    asm volatile("ldmatrix.sync.aligned.m8n8.x4.shared.b16 {%0,%1,%2,%3}, [%4];"
        : "=r"(r0), "=r"(r1), "=r"(r2), "=r"(r3) : "r"(a));
}
__device__ __forceinline__ void ldsm4t(uint32_t& r0, uint32_t& r1, uint32_t& r2, uint32_t& r3, uint32_t a) {
    asm volatile("ldmatrix.sync.aligned.m8n8.x4.trans.shared.b16 {%0,%1,%2,%3}, [%4];"
        : "=r"(r0), "=r"(r1), "=r"(r2), "=r"(r3) : "r"(a));
}
__device__ __forceinline__ void mma16(float* d, const uint32_t* a, const uint32_t* b) {
    asm volatile("mma.sync.aligned.m16n8k16.row.col.f32.f16.f16.f32 "
        "{%0,%1,%2,%3}, {%4,%5,%6,%7}, {%8,%9}, {%0,%1,%2,%3};"
        : "+f"(d[0]), "+f"(d[1]), "+f"(d[2]), "+f"(d[3])
        : "r"(a[0]), "r"(a[1]), "r"(a[2]), "r"(a[3]), "r"(b[0]), "r"(b[1]));
}
__device__ __forceinline__ void cpa16s(uint32_t s, const void* g) {
    asm volatile("cp.async.cg.shared.global [%0], [%1], 16;" :: "r"(s), "l"(g));
}
__device__ __forceinline__ void cpcommit() { asm volatile("cp.async.commit_group;"); }
template <int N> __device__ __forceinline__ void cpwait() {
    asm volatile("cp.async.wait_group %0;" :: "n"(N));
}
#define ROT3(a, b, c) { uint32_t t_ = a; a = b; b = c; c = t_; }

// ---------------------------------------------------------------------------
__global__ __launch_bounds__(256) void k_prep(const float* __restrict__ w_in,
                                              const float* __restrict__ w_ff) {
    int i = blockIdx.x * 256 + threadIdx.x;
    if (i < C3 * C) g_winh[i] = __float2half_rn(w_in[i]);
    if (i < C * C)  g_wffh[i] = __float2half_rn(w_ff[i]);
}

// x[n][c][t][v] fp32 -> xT[n][c][v][t] fp16
__global__ __launch_bounds__(256) void k_tr(const float* __restrict__ x) {
    __shared__ float sm[TV];
    size_t base = (size_t)blockIdx.x * TV;
    const int tid = threadIdx.x;
#pragma unroll
    for (int j = 0; j < 25; j++) sm[tid + j * 256] = x[base + tid + j * 256];
    __syncthreads();
#pragma unroll
    for (int j = 0; j < 25; j++) {
        int o = tid + j * 256;
        int t = o & 255, v = o >> 8;
        g_xTh[base + o] = __float2half_rn(sm[t * 25 + v]);
    }
}

// ---------------------------------------------------------------------------
// QKV: qkv[d][(v,t)] = w*xT + b.  M=576 N=6400 K=192. Block 64x256, warp 32x64.
// BK=32, NIT=6. Epilogue staged through smem for 128B-coalesced writes.
// ---------------------------------------------------------------------------
__global__ __launch_bounds__(256) void k_qkv(const float* __restrict__ bias) {
    constexpr int PA = 40, PB = 264;
    constexpr int ABH = 64 * PA, BBH = 32 * PB;
    __shared__ __align__(16) __half sh[3 * (ABH + BBH)];
    const int bz = blockIdx.z, m0 = blockIdx.y * 64, n0 = blockIdx.x * 256;
    const int tid = threadIdx.x, lane = tid & 31, wid = tid >> 5;
    const int g = lane >> 2, tg = lane & 3;
    const int wm = (wid >> 2) * 32, wn = (wid & 3) * 64;
    const __half* Bg = g_xTh + (size_t)bz * C * TV + n0;
    uint32_t sb = (uint32_t)__cvta_generic_to_shared(sh);
    uint32_t A0 = sb, B0 = sb + 3 * ABH * 2;

    uint32_t aLO = (((lane & 15)) * PA + (lane >> 4) * 8) * 2;
    uint32_t aF[2][2];
#pragma unroll
    for (int mi = 0; mi < 2; mi++)
#pragma unroll
        for (int ks = 0; ks < 2; ks++)
            aF[mi][ks] = aLO + ((wm + mi * 16) * PA + ks * 16) * 2;
    uint32_t bLO = (((lane & 7) + ((lane >> 3) & 1) * 8) * PB + (lane >> 4) * 8) * 2;
    uint32_t bF[4][2];
#pragma unroll
    for (int j = 0; j < 4; j++)
#pragma unroll
        for (int ks = 0; ks < 2; ks++)
            bF[j][ks] = bLO + (wn + j * 16) * 2 + ks * 16 * PB * 2;

    const int arow = tid >> 2, ac8 = (tid & 3) * 8;
    const uint32_t aSt = (arow * PA + ac8) * 2;
    const int brow = tid >> 3, bc0 = (tid & 7) * 32;

    float acc[2][8][4] = {};

    auto LOAD = [&](uint32_t aB, uint32_t bB, int kk) {
        cpa16s(aB + aSt, g_winh + (m0 + arow) * C + kk + ac8);
#pragma unroll
        for (int i = 0; i < 4; i++)
            cpa16s(bB + (brow * PB + bc0 + i * 8) * 2,
                   Bg + (size_t)(kk + brow) * TV + bc0 + i * 8);
    };
    auto COMP = [&](uint32_t aB, uint32_t bB) {
#pragma unroll
        for (int ks = 0; ks < 2; ks++) {
            uint32_t a[2][4], b[8][2];
#pragma unroll
            for (int mi = 0; mi < 2; mi++)
                ldsm4(a[mi][0], a[mi][1], a[mi][2], a[mi][3], aB + aF[mi][ks]);
#pragma unroll
            for (int j = 0; j < 4; j++)
                ldsm4t(b[2 * j][0], b[2 * j][1], b[2 * j + 1][0], b[2 * j + 1][1], bB + bF[j][ks]);
#pragma unroll
            for (int mi = 0; mi < 2; mi++)
#pragma unroll
                for (int ni = 0; ni < 8; ni++) mma16(acc[mi][ni], a[mi], b[ni]);
        }
    };

    uint32_t aC = A0, aN = A0 + ABH * 2, aL = A0 + 2 * ABH * 2;
    uint32_t bC = B0, bN = B0 + BBH * 2, bL = B0 + 2 * BBH * 2;
    LOAD(aC, bC, 0); cpcommit();
    LOAD(aN, bN, 32); cpcommit();
    int kk = 64;
    const int NIT = 6;
#pragma unroll 1
    for (int it = 0; it < NIT; ++it) {
        cpwait<1>(); __syncthreads();
        if (it + 2 < NIT) { LOAD(aL, bL, kk); kk += 32; }
        COMP(aC, bC);
        cpcommit();
        ROT3(aC, aN, aL); ROT3(bC, bN, bL);
    }
    // --- staged epilogue: acc -> smem (pitch 264) -> coalesced 16B writes ---
    __syncthreads();
    __half* St = sh;
#pragma unroll
    for (int mi = 0; mi < 2; mi++) {
        int r0 = wm + mi * 16 + g;
        int rg = m0 + r0;
        float b0 = bias[rg], b1 = bias[rg + 8];
#pragma unroll
        for (int ni = 0; ni < 8; ni++) {
            int col = wn + ni * 8 + 2 * tg;
            *(__half2*)&St[r0 * 264 + col] =
                __floats2half2_rn(acc[mi][ni][0] + b0, acc[mi][ni][1] + b0);
            *(__half2*)&St[(r0 + 8) * 264 + col] =
                __floats2half2_rn(acc[mi][ni][2] + b1, acc[mi][ni][3] + b1);
        }
    }
    __syncthreads();
#pragma unroll
    for (int it = 0; it < 8; ++it) {
        int c = tid + it * 256;
        int row = c >> 5, cc = (c & 31) * 8;
        *(uint4*)(g_qkvh + (size_t)(bz * C3 + m0 + row) * TV + n0 + cc) =
            *(uint4*)&St[row * 264 + cc];
    }
}

// ---------------------------------------------------------------------------
// Scores: att[q][t] = tanh(sum_k K[k][q]*Q[k][t]/1600). K=1600, BK=32, NIT=50.
// Block 64(q)x128(t), warp 32x32. (unchanged from round 8)
// ---------------------------------------------------------------------------
__global__ __launch_bounds__(256) void k_att() {
    constexpr int PA = 72, PB = 136;
    constexpr int ABH = 32 * PA, BBH = 32 * PB;
    __shared__ __align__(16) __half sh[3 * (ABH + BBH)];
    const int bz = blockIdx.z;
    const int nb = bz / 3, s = bz - nb * 3;
    const int m0 = blockIdx.y * 64, n0 = blockIdx.x * 128;
    const int tid = threadIdx.x, lane = tid & 31, wid = tid >> 5;
    const int g = lane >> 2, tg = lane & 3;
    const int wm = (wid >> 2) * 32, wn = (wid & 3) * 32;
    const __half* Ag = g_qkvh + ((size_t)nb * C3 + C + s * MID) * TV + m0;
    const __half* Bg = g_qkvh + ((size_t)nb * C3 + s * MID) * TV + n0;
    uint32_t sb = (uint32_t)__cvta_generic_to_shared(sh);
    uint32_t A0 = sb, B0 = sb + 3 * ABH * 2;

    uint32_t aLO = (((lane & 7) + (lane >> 4) * 8) * PA + ((lane >> 3) & 1) * 8) * 2;
    uint32_t aF[2][2];
#pragma unroll
    for (int mi = 0; mi < 2; mi++)
#pragma unroll
        for (int ks = 0; ks < 2; ks++)
            aF[mi][ks] = aLO + (wm + mi * 16) * 2 + ks * 16 * PA * 2;
    uint32_t bLO = (((lane & 7) + ((lane >> 3) & 1) * 8) * PB + (lane >> 4) * 8) * 2;
    uint32_t bF[2][2];
#pragma unroll
    for (int j = 0; j < 2; j++)
#pragma unroll
        for (int ks = 0; ks < 2; ks++)
            bF[j][ks] = bLO + (wn + j * 16) * 2 + ks * 16 * PB * 2;

    const int arow = tid >> 3, ac8 = (tid & 7) * 8;
    const uint32_t aSt = (arow * PA + ac8) * 2;
    const int brow = tid >> 4, bc8 = (tid & 15) * 8;

    float acc[2][4][4] = {};

    auto LOAD = [&](uint32_t aB, uint32_t bB, int kk) {
        cpa16s(aB + aSt, Ag + (size_t)(kk + arow) * T + ac8);
        cpa16s(bB + (brow * PB + bc8) * 2, Bg + (size_t)(kk + brow) * T + bc8);
        cpa16s(bB + ((brow + 16) * PB + bc8) * 2, Bg + (size_t)(kk + brow + 16) * T + bc8);
    };
    auto COMP = [&](uint32_t aB, uint32_t bB) {
#pragma unroll
        for (int ks = 0; ks < 2; ks++) {
            uint32_t a[2][4], b[4][2];
#pragma unroll
            for (int mi = 0; mi < 2; mi++)
                ldsm4t(a[mi][0], a[mi][1], a[mi][2], a[mi][3], aB + aF[mi][ks]);
#pragma unroll
            for (int j = 0; j < 2; j++)
                ldsm4t(b[2 * j][0], b[2 * j][1], b[2 * j + 1][0], b[2 * j + 1][1], bB + bF[j][ks]);
#pragma unroll
            for (int mi = 0; mi < 2; mi++)
#pragma unroll
                for (int ni = 0; ni < 4; ni++) mma16(acc[mi][ni], a[mi], b[ni]);
        }
    };

    uint32_t aC = A0, aN = A0 + ABH * 2, aL = A0 + 2 * ABH * 2;
    uint32_t bC = B0, bN = B0 + BBH * 2, bL = B0 + 2 * BBH * 2;
    LOAD(aC, bC, 0); cpcommit();
    LOAD(aN, bN, 32); cpcommit();
    int kk = 64;
    const int NIT = 50;
#pragma unroll 1
    for (int it = 0; it < NIT; ++it) {
        cpwait<1>(); __syncthreads();
        if (it + 2 < NIT) { LOAD(aL, bL, kk); kk += 32; }
        COMP(aC, bC);
        cpcommit();
        ROT3(aC, aN, aL); ROT3(bC, bN, bL);
    }
    const float scl = 1.f / 1600.f;
#pragma unroll
    for (int mi = 0; mi < 2; mi++) {
        int q0r = m0 + wm + mi * 16 + g;
#pragma unroll
        for (int ni = 0; ni < 4; ni++) {
            int col = n0 + wn + ni * 8 + 2 * tg;
            *(__half2*)&g_atth[((size_t)bz * T + q0r) * T + col] =
                __floats2half2_rn(tanhf(acc[mi][ni][0] * scl), tanhf(acc[mi][ni][1] * scl));
            *(__half2*)&g_atth[((size_t)bz * T + q0r + 8) * T + col] =
                __floats2half2_rn(tanhf(acc[mi][ni][2] * scl), tanhf(acc[mi][ni][3] * scl));
        }
    }
}

// ---------------------------------------------------------------------------
// att.V: y[(c,v)][t] = sum_q V[(c,v)][q] * att[q][t]. K=256, BK=32, NIT=8.
// Block 64x256, warp 32x64 (clone of k_qkv mainloop). Staged fp16 epilogue.
// ---------------------------------------------------------------------------
__global__ __launch_bounds__(256) void k_av() {
    constexpr int PA = 40, PB = 264;
    constexpr int ABH = 64 * PA, BBH = 32 * PB;
    __shared__ __align__(16) __half sh[3 * (ABH + BBH)];
    const int bz = blockIdx.y;
    const int nb = bz / 3, s = bz - nb * 3;
    const int m0 = blockIdx.x * 64;
    const int tid = threadIdx.x, lane = tid & 31, wid = tid >> 5;
    const int g = lane >> 2, tg = lane & 3;
    const int wm = (wid >> 2) * 32, wn = (wid & 3) * 64;
    const __half* Ag = g_qkvh + ((size_t)nb * C3 + 2 * C + s * MID) * TV;  // V [m][k]
    const __half* Bg = g_atth + (size_t)bz * T * T;                        // att [q][t]
    uint32_t sb = (uint32_t)__cvta_generic_to_shared(sh);
    uint32_t A0 = sb, B0 = sb + 3 * ABH * 2;

    uint32_t aLO = (((lane & 15)) * PA + (lane >> 4) * 8) * 2;
    uint32_t aF[2][2];
#pragma unroll
    for (int mi = 0; mi < 2; mi++)
#pragma unroll
        for (int ks = 0; ks < 2; ks++)
            aF[mi][ks] = aLO + ((wm + mi * 16) * PA + ks * 16) * 2;
    uint32_t bLO = (((lane & 7) + ((lane >> 3) & 1) * 8) * PB + (lane >> 4) * 8) * 2;
    uint32_t bF[4][2];
#pragma unroll
    for (int j = 0; j < 4; j++)
#pragma unroll
        for (int ks = 0; ks < 2; ks++)
            bF[j][ks] = bLO + (wn + j * 16) * 2 + ks * 16 * PB * 2;

    const int arow = tid >> 2, ac8 = (tid & 3) * 8;
    const uint32_t aSt = (arow * PA + ac8) * 2;
    const int brow = tid >> 3, bc0 = (tid & 7) * 32;

    float acc[2][8][4] = {};

    auto LOAD = [&](uint32_t aB, uint32_t bB, int kk) {
        cpa16s(aB + aSt, Ag + (size_t)(m0 + arow) * T + kk + ac8);
#pragma unroll
        for (int i = 0; i < 4; i++)
            cpa16s(bB + (brow * PB + bc0 + i * 8) * 2,
                   Bg + (size_t)(kk + brow) * T + bc0 + i * 8);
    };
    auto COMP = [&](uint32_t aB, uint32_t bB) {
#pragma unroll
        for (int ks = 0; ks < 2; ks++) {
            uint32_t a[2][4], b[8][2];
#pragma unroll
            for (int mi = 0; mi < 2; mi++)
                ldsm4(a[mi][0], a[mi][1], a[mi][2], a[mi][3], aB + aF[mi][ks]);
#pragma unroll
            for (int j = 0; j < 4; j++)
                ldsm4t(b[2 * j][0], b[2 * j][1], b[2 * j + 1][0], b[2 * j + 1][1], bB + bF[j][ks]);
#pragma unroll
            for (int mi = 0; mi < 2; mi++)
#pragma unroll
                for (int ni = 0; ni < 8; ni++) mma16(acc[mi][ni], a[mi], b[ni]);
        }
    };

    uint32_t aC = A0, aN = A0 + ABH * 2, aL = A0 + 2 * ABH * 2;
    uint32_t bC = B0, bN = B0 + BBH * 2, bL = B0 + 2 * BBH * 2;
    LOAD(aC, bC, 0); cpcommit();
    LOAD(aN, bN, 32); cpcommit();
    int kk = 64;
    const int NIT = 8;
#pragma unroll 1
    for (int it = 0; it < NIT; ++it) {
        cpwait<1>(); __syncthreads();
        if (it + 2 < NIT) { LOAD(aL, bL, kk); kk += 32; }
        COMP(aC, bC);
        cpcommit();
        ROT3(aC, aN, aL); ROT3(bC, bN, bL);
    }
    // --- staged epilogue: acc -> smem fp16 (pitch 264) -> scatter to y[ch][t][v] ---
    __syncthreads();
    __half* St = sh;
#pragma unroll
    for (int mi = 0; mi < 2; mi++) {
        int r0 = wm + mi * 16 + g;
#pragma unroll
        for (int ni = 0; ni < 8; ni++) {
            int col = wn + ni * 8 + 2 * tg;
            *(__half2*)&St[r0 * 264 + col] =
                __floats2half2_rn(acc[mi][ni][0], acc[mi][ni][1]);
            *(__half2*)&St[(r0 + 8) * 264 + col] =
                __floats2half2_rn(acc[mi][ni][2], acc[mi][ni][3]);
        }
    }
    __syncthreads();
    const int chbase = nb * C + s * MID;
#pragma unroll
    for (int it = 0; it < 64; ++it) {
        int e = tid + it * 256;
        int m = e & 63, t = e >> 6;
        int mg = m0 + m;
        int c = mg / 25, v = mg - c * 25;
        g_yh[((size_t)(chbase + c) * T + t) * V + v] = St[m * 264 + t];
    }
}

// ---------------------------------------------------------------------------
// FF + BN + residual + LeakyReLU. M=192 N=6400 K=192. Block 64x256, warp 32x64.
// ---------------------------------------------------------------------------
__global__ __launch_bounds__(256) void k_ff(const float* __restrict__ x,
                                            const float* __restrict__ bias,
                                            const float* __restrict__ gamma,
                                            const float* __restrict__ beta,
                                            const float* __restrict__ mean,
                                            const float* __restrict__ var,
                                            float* __restrict__ out) {
    constexpr int PA = 40, PB = 264;
    constexpr int ABH = 64 * PA, BBH = 32 * PB;
    __shared__ __align__(16) __half sh[3 * (ABH + BBH)];
    const int bz = blockIdx.z, m0 = blockIdx.y * 64, n0 = blockIdx.x * 256;
    const int tid = threadIdx.x, lane = tid & 31, wid = tid >> 5;
    const int g = lane >> 2, tg = lane & 3;
    const int wm = (wid >> 2) * 32, wn = (wid & 3) * 64;
    const __half* Bg = g_yh + (size_t)bz * C * TV + n0;
    uint32_t sb = (uint32_t)__cvta_generic_to_shared(sh);
    uint32_t A0 = sb, B0 = sb + 3 * ABH * 2;

    uint32_t aLO = (((lane & 15)) * PA + (lane >> 4) * 8) * 2;
    uint32_t aF[2][2];
#pragma unroll
    for (int mi = 0; mi < 2; mi++)
#pragma unroll
        for (int ks = 0; ks < 2; ks++)
            aF[mi][ks] = aLO + ((wm + mi * 16) * PA + ks * 16) * 2;
    uint32_t bLO = (((lane & 7) + ((lane >> 3) & 1) * 8) * PB + (lane >> 4) * 8) * 2;
    uint32_t bF[4][2];
#pragma unroll
    for (int j = 0; j < 4; j++)
#pragma unroll
        for (int ks = 0; ks < 2; ks++)
            bF[j][ks] = bLO + (wn + j * 16) * 2 + ks * 16 * PB * 2;

    const int arow = tid >> 2, ac8 = (tid & 3) * 8;
    const uint32_t aSt = (arow * PA + ac8) * 2;
    const int brow = tid >> 3, bc0 = (tid & 7) * 32;

    float acc[2][8][4] = {};

    auto LOAD = [&](uint32_t aB, uint32_t bB, int kk) {
        cpa16s(aB + aSt, g_wffh + (m0 + arow) * C + kk + ac8);
#pragma unroll
        for (int i = 0; i < 4; i++)
            cpa16s(bB + (brow * PB + bc0 + i * 8) * 2,
                   Bg + (size_t)(kk + brow) * TV + bc0 + i * 8);
    };
    auto COMP = [&](uint32_t aB, uint32_t bB) {
#pragma unroll
        for (int ks = 0; ks < 2; ks++) {
            uint32_t a[2][4], b[8][2];
#pragma unroll
            for (int mi = 0; mi < 2; mi++)
                ldsm4(a[mi][0], a[mi][1], a[mi][2], a[mi][3], aB + aF[mi][ks]);
#pragma unroll
            for (int j = 0; j < 4; j++)
                ldsm4t(b[2 * j][0], b[2 * j][1], b[2 * j + 1][0], b[2 * j + 1][1], bB + bF[j][ks]);
#pragma unroll
            for (int mi = 0; mi < 2; mi++)
#pragma unroll
                for (int ni = 0; ni < 8; ni++) mma16(acc[mi][ni], a[mi], b[ni]);
        }
    };

    uint32_t aC = A0, aN = A0 + ABH * 2, aL = A0 + 2 * ABH * 2;
    uint32_t bC = B0, bN = B0 + BBH * 2, bL = B0 + 2 * BBH * 2;
    LOAD(aC, bC, 0); cpcommit();
    LOAD(aN, bN, 32); cpcommit();
    int kk = 64;
    const int NIT = 6;
#pragma unroll 1
    for (int it = 0; it < NIT; ++it) {
        cpwait<1>(); __syncthreads();
        if (it + 2 < NIT) { LOAD(aL, bL, kk); kk += 32; }
        COMP(aC, bC);
        cpcommit();
        ROT3(aC, aN, aL); ROT3(bC, bN, bL);
    }
#pragma unroll
    for (int mi = 0; mi < 2; mi++) {
        int r0 = m0 + wm + mi * 16 + g;
        int r1 = r0 + 8;
        float sc0 = gamma[r0] * rsqrtf(var[r0] + 1e-5f);
        float sh0 = beta[r0] - mean[r0] * sc0;
        float bb0 = bias[r0];
        float sc1 = gamma[r1] * rsqrtf(var[r1] + 1e-5f);
        float sh1 = beta[r1] - mean[r1] * sc1;
        float bb1 = bias[r1];
#pragma unroll
        for (int ni = 0; ni < 8; ni++) {
            int col = n0 + wn + ni * 8 + 2 * tg;
            size_t i0 = (size_t)(bz * C + r0) * TV + col;
            size_t i1 = (size_t)(bz * C + r1) * TV + col;
            float2 x0 = *(const float2*)&x[i0];
            float2 x1 = *(const float2*)&x[i1];
            float z, o0x, o0y, o1x, o1y;
            z = x0.x + (acc[mi][ni][0] + bb0) * sc0 + sh0; o0x = z >= 0.f ? z : 0.1f * z;
            z = x0.y + (acc[mi][ni][1] + bb0) * sc0 + sh0; o0y = z >= 0.f ? z : 0.1f * z;
            z = x1.x + (acc[mi][ni][2] + bb1) * sc1 + sh1; o1x = z >= 0.f ? z : 0.1f * z;
            z = x1.y + (acc[mi][ni][3] + bb1) * sc1 + sh1; o1y = z >= 0.f ? z : 0.1f * z;
            *(float2*)&out[i0] = make_float2(o0x, o0y);
            *(float2*)&out[i1] = make_float2(o1x, o1y);
        }
    }
}

extern "C" void kernel_launch(void* const* d_in, const int* in_sizes, int n_in,
                              void* d_out, int out_size) {
    const float* x     = (const float*)d_in[0];
    const float* w_in  = (const float*)d_in[1];
    const float* b_in  = (const float*)d_in[2];
    const float* w_ff  = (const float*)d_in[3];
    const float* b_ff  = (const float*)d_in[4];
    const float* gamma = (const float*)d_in[5];
    const float* beta  = (const float*)d_in[6];
    const float* mean  = (const float*)d_in[7];
    const float* var   = (const float*)d_in[8];
    float* out = (float*)d_out;

    k_prep<<<432, 256>>>(w_in, w_ff);
    k_tr <<<NBATCH * C, 256>>>(x);
    k_qkv<<<dim3(25, 9, 32), 256>>>(b_in);
    k_att<<<dim3(2, 4, 96), 256>>>();
    k_av <<<dim3(25, 96), 256>>>();
    k_ff <<<dim3(25, 3, 32), 256>>>(x, b_ff, gamma, beta, mean, var, out);
}

// round 11
// speedup vs baseline: 1.1968x; 1.1968x over previous
#include <cuda_runtime.h>
#include <cuda_fp16.h>
#include <cstdint>

#define NBATCH 32
#define C 192
#define C3 576
#define T 256
#define V 25
#define TV 6400
#define S 3
#define MID 64

// fp16 scratch (device globals)
__device__ __half g_xTh [NBATCH * C  * TV];   // [n][c][v][t]
__device__ __half g_qkvh[NBATCH * C3 * TV];   // [n][d][(v,t)]
__device__ __half g_atth[NBATCH * S * T * T]; // [ns][q][t]
__device__ __half g_yh  [NBATCH * C  * TV];   // [n][ch][t][v]
__device__ __half g_winh[C3 * C];
__device__ __half g_wffh[C * C];

__device__ __forceinline__ void ldsm4(uint32_t& r0, uint32_t& r1, uint32_t& r2, uint32_t& r3, uint32_t a) {
    asm volatile("ldmatrix.sync.aligned.m8n8.x4.shared.b16 {%0,%1,%2,%3}, [%4];"
        : "=r"(r0), "=r"(r1), "=r"(r2), "=r"(r3) : "r"(a));
}
__device__ __forceinline__ void ldsm4t(uint32_t& r0, uint32_t& r1, uint32_t& r2, uint32_t& r3, uint32_t a) {
    asm volatile("ldmatrix.sync.aligned.m8n8.x4.trans.shared.b16 {%0,%1,%2,%3}, [%4];"
        : "=r"(r0), "=r"(r1), "=r"(r2), "=r"(r3) : "r"(a));
}
__device__ __forceinline__ void mma16(float* d, const uint32_t* a, const uint32_t* b) {
    asm volatile("mma.sync.aligned.m16n8k16.row.col.f32.f16.f16.f32 "
        "{%0,%1,%2,%3}, {%4,%5,%6,%7}, {%8,%9}, {%0,%1,%2,%3};"
        : "+f"(d[0]), "+f"(d[1]), "+f"(d[2]), "+f"(d[3])
        : "r"(a[0]), "r"(a[1]), "r"(a[2]), "r"(a[3]), "r"(b[0]), "r"(b[1]));
}
__device__ __forceinline__ void cpa16s(uint32_t s, const void* g) {
    asm volatile("cp.async.cg.shared.global [%0], [%1], 16;" :: "r"(s), "l"(g));
}
__device__ __forceinline__ void cpcommit() { asm volatile("cp.async.commit_group;"); }
template <int N> __device__ __forceinline__ void cpwait() {
    asm volatile("cp.async.wait_group %0;" :: "n"(N));
}
#define ROT3(a, b, c) { uint32_t t_ = a; a = b; b = c; c = t_; }

// ---------------------------------------------------------------------------
__global__ __launch_bounds__(256) void k_prep(const float* __restrict__ w_in,
                                              const float* __restrict__ w_ff) {
    int i = blockIdx.x * 256 + threadIdx.x;
    if (i < C3 * C) g_winh[i] = __float2half_rn(w_in[i]);
    if (i < C * C)  g_wffh[i] = __float2half_rn(w_ff[i]);
}

// x[n][c][t][v] fp32 -> xT[n][c][v][t] fp16
__global__ __launch_bounds__(256) void k_tr(const float* __restrict__ x) {
    __shared__ float sm[TV];
    size_t base = (size_t)blockIdx.x * TV;
    const int tid = threadIdx.x;
#pragma unroll
    for (int j = 0; j < 25; j++) sm[tid + j * 256] = x[base + tid + j * 256];
    __syncthreads();
#pragma unroll
    for (int j = 0; j < 25; j++) {
        int o = tid + j * 256;
        int t = o & 255, v = o >> 8;
        g_xTh[base + o] = __float2half_rn(sm[t * 25 + v]);
    }
}

// ---------------------------------------------------------------------------
// QKV: M=576 N=6400 K=192. Block 64x256, 4 warps, warp tile 64x64. BK=32, NIT=6.
// ---------------------------------------------------------------------------
__global__ __launch_bounds__(128) void k_qkv(const float* __restrict__ bias) {
    constexpr int PA = 40, PB = 264;
    constexpr int ABH = 64 * PA, BBH = 32 * PB;
    __shared__ __align__(16) __half sh[3 * (ABH + BBH)];
    const int bz = blockIdx.z, m0 = blockIdx.y * 64, n0 = blockIdx.x * 256;
    const int tid = threadIdx.x, lane = tid & 31, wid = tid >> 5;
    const int g = lane >> 2, tg = lane & 3;
    const int wn = wid * 64;
    const __half* Bg = g_xTh + (size_t)bz * C * TV + n0;
    uint32_t sb = (uint32_t)__cvta_generic_to_shared(sh);
    uint32_t A0 = sb, B0 = sb + 3 * ABH * 2;

    uint32_t aLO = ((lane & 15) * PA + (lane >> 4) * 8) * 2;
    uint32_t aF[4][2];
#pragma unroll
    for (int mi = 0; mi < 4; mi++)
#pragma unroll
        for (int ks = 0; ks < 2; ks++)
            aF[mi][ks] = aLO + ((mi * 16) * PA + ks * 16) * 2;
    uint32_t bLO = (((lane & 7) + ((lane >> 3) & 1) * 8) * PB + (lane >> 4) * 8) * 2;
    uint32_t bF[4][2];
#pragma unroll
    for (int j = 0; j < 4; j++)
#pragma unroll
        for (int ks = 0; ks < 2; ks++)
            bF[j][ks] = bLO + (wn + j * 16) * 2 + ks * 16 * PB * 2;

    float acc[4][8][4] = {};

    auto LOAD = [&](uint32_t aB, uint32_t bB, int kk) {
#pragma unroll
        for (int i = 0; i < 2; i++) {
            int e = tid + i * 128;
            int r = e >> 2, c = e & 3;
            cpa16s(aB + r * PA * 2 + c * 16, g_winh + (m0 + r) * C + kk + c * 8);
        }
#pragma unroll
        for (int i = 0; i < 8; i++) {
            int e = tid + i * 128;
            int r = e >> 5, c = e & 31;
            cpa16s(bB + r * PB * 2 + c * 16, Bg + (size_t)(kk + r) * TV + c * 8);
        }
    };
    auto COMP = [&](uint32_t aB, uint32_t bB) {
#pragma unroll
        for (int ks = 0; ks < 2; ks++) {
            uint32_t a[4][4], b[8][2];
#pragma unroll
            for (int mi = 0; mi < 4; mi++)
                ldsm4(a[mi][0], a[mi][1], a[mi][2], a[mi][3], aB + aF[mi][ks]);
#pragma unroll
            for (int j = 0; j < 4; j++)
                ldsm4t(b[2 * j][0], b[2 * j][1], b[2 * j + 1][0], b[2 * j + 1][1], bB + bF[j][ks]);
#pragma unroll
            for (int mi = 0; mi < 4; mi++)
#pragma unroll
                for (int ni = 0; ni < 8; ni++) mma16(acc[mi][ni], a[mi], b[ni]);
        }
    };

    uint32_t aC = A0, aN = A0 + ABH * 2, aL = A0 + 2 * ABH * 2;
    uint32_t bC = B0, bN = B0 + BBH * 2, bL = B0 + 2 * BBH * 2;
    LOAD(aC, bC, 0); cpcommit();
    LOAD(aN, bN, 32); cpcommit();
    int kk = 64;
    const int NIT = 6;
#pragma unroll 1
    for (int it = 0; it < NIT; ++it) {
        cpwait<1>(); __syncthreads();
        if (it + 2 < NIT) { LOAD(aL, bL, kk); kk += 32; }
        COMP(aC, bC);
        cpcommit();
        ROT3(aC, aN, aL); ROT3(bC, bN, bL);
    }
#pragma unroll
    for (int mi = 0; mi < 4; mi++) {
        int r0 = m0 + mi * 16 + g;
        float b0 = bias[r0], b1 = bias[r0 + 8];
#pragma unroll
        for (int ni = 0; ni < 8; ni++) {
            int col = n0 + wn + ni * 8 + 2 * tg;
            *(__half2*)&g_qkvh[(size_t)(bz * C3 + r0) * TV + col] =
                __floats2half2_rn(acc[mi][ni][0] + b0, acc[mi][ni][1] + b0);
            *(__half2*)&g_qkvh[(size_t)(bz * C3 + r0 + 8) * TV + col] =
                __floats2half2_rn(acc[mi][ni][2] + b1, acc[mi][ni][3] + b1);
        }
    }
}

// ---------------------------------------------------------------------------
// Scores: att[q][t] = tanh(sum_k K[k][q]*Q[k][t]/1600). K=1600, BK=32, NIT=50.
// Block 128x128, 4 warps (2x2), warp tile 64x64.
// ---------------------------------------------------------------------------
__global__ __launch_bounds__(128) void k_att() {
    constexpr int PA = 136, PB = 136;
    constexpr int ABH = 32 * PA, BBH = 32 * PB;
    __shared__ __align__(16) __half sh[3 * (ABH + BBH)];
    const int bz = blockIdx.z;
    const int nb = bz / 3, s = bz - nb * 3;
    const int m0 = blockIdx.y * 128, n0 = blockIdx.x * 128;
    const int tid = threadIdx.x, lane = tid & 31, wid = tid >> 5;
    const int g = lane >> 2, tg = lane & 3;
    const int wm = (wid >> 1) * 64, wn = (wid & 1) * 64;
    const __half* Ag = g_qkvh + ((size_t)nb * C3 + C + s * MID) * TV + m0;  // K [k][m]
    const __half* Bg = g_qkvh + ((size_t)nb * C3 + s * MID) * TV + n0;      // Q [k][n]
    uint32_t sb = (uint32_t)__cvta_generic_to_shared(sh);
    uint32_t A0 = sb, B0 = sb + 3 * ABH * 2;

    uint32_t aLO = (((lane & 7) + (lane >> 4) * 8) * PA + ((lane >> 3) & 1) * 8) * 2;
    uint32_t aF[4][2];
#pragma unroll
    for (int mi = 0; mi < 4; mi++)
#pragma unroll
        for (int ks = 0; ks < 2; ks++)
            aF[mi][ks] = aLO + (wm + mi * 16) * 2 + ks * 16 * PA * 2;
    uint32_t bLO = (((lane & 7) + ((lane >> 3) & 1) * 8) * PB + (lane >> 4) * 8) * 2;
    uint32_t bF[4][2];
#pragma unroll
    for (int j = 0; j < 4; j++)
#pragma unroll
        for (int ks = 0; ks < 2; ks++)
            bF[j][ks] = bLO + (wn + j * 16) * 2 + ks * 16 * PB * 2;

    float acc[4][8][4] = {};

    auto LOAD = [&](uint32_t aB, uint32_t bB, int kk) {
#pragma unroll
        for (int i = 0; i < 4; i++) {
            int e = tid + i * 128;
            int r = e >> 4, c = e & 15;
            cpa16s(aB + r * PA * 2 + c * 16, Ag + (size_t)(kk + r) * T + c * 8);
        }
#pragma unroll
        for (int i = 0; i < 4; i++) {
            int e = tid + i * 128;
            int r = e >> 4, c = e & 15;
            cpa16s(bB + r * PB * 2 + c * 16, Bg + (size_t)(kk + r) * T + c * 8);
        }
    };
    auto COMP = [&](uint32_t aB, uint32_t bB) {
#pragma unroll
        for (int ks = 0; ks < 2; ks++) {
            uint32_t a[4][4], b[8][2];
#pragma unroll
            for (int mi = 0; mi < 4; mi++)
                ldsm4t(a[mi][0], a[mi][1], a[mi][2], a[mi][3], aB + aF[mi][ks]);
#pragma unroll
            for (int j = 0; j < 4; j++)
                ldsm4t(b[2 * j][0], b[2 * j][1], b[2 * j + 1][0], b[2 * j + 1][1], bB + bF[j][ks]);
#pragma unroll
            for (int mi = 0; mi < 4; mi++)
#pragma unroll
                for (int ni = 0; ni < 8; ni++) mma16(acc[mi][ni], a[mi], b[ni]);
        }
    };

    uint32_t aC = A0, aN = A0 + ABH * 2, aL = A0 + 2 * ABH * 2;
    uint32_t bC = B0, bN = B0 + BBH * 2, bL = B0 + 2 * BBH * 2;
    LOAD(aC, bC, 0); cpcommit();
    LOAD(aN, bN, 32); cpcommit();
    int kk = 64;
    const int NIT = 50;
#pragma unroll 1
    for (int it = 0; it < NIT; ++it) {
        cpwait<1>(); __syncthreads();
        if (it + 2 < NIT) { LOAD(aL, bL, kk); kk += 32; }
        COMP(aC, bC);
        cpcommit();
        ROT3(aC, aN, aL); ROT3(bC, bN, bL);
    }
    const float scl = 1.f / 1600.f;
#pragma unroll
    for (int mi = 0; mi < 4; mi++) {
        int q0r = m0 + wm + mi * 16 + g;
#pragma unroll
        for (int ni = 0; ni < 8; ni++) {
            int col = n0 + wn + ni * 8 + 2 * tg;
            *(__half2*)&g_atth[((size_t)bz * T + q0r) * T + col] =
                __floats2half2_rn(tanhf(acc[mi][ni][0] * scl), tanhf(acc[mi][ni][1] * scl));
            *(__half2*)&g_atth[((size_t)bz * T + q0r + 8) * T + col] =
                __floats2half2_rn(tanhf(acc[mi][ni][2] * scl), tanhf(acc[mi][ni][3] * scl));
        }
    }
}

// ---------------------------------------------------------------------------
// att.V: M=1600 N=256 K=256. Block 64x256, 4 warps, warp 64x64. BK=32, NIT=8.
// Staged fp16 epilogue -> scatter y[ch][t][v].
// ---------------------------------------------------------------------------
__global__ __launch_bounds__(128) void k_av() {
    constexpr int PA = 40, PB = 264;
    constexpr int ABH = 64 * PA, BBH = 32 * PB;
    __shared__ __align__(16) __half sh[3 * (ABH + BBH)];
    const int bz = blockIdx.y;
    const int nb = bz / 3, s = bz - nb * 3;
    const int m0 = blockIdx.x * 64;
    const int tid = threadIdx.x, lane = tid & 31, wid = tid >> 5;
    const int g = lane >> 2, tg = lane & 3;
    const int wn = wid * 64;
    const __half* Ag = g_qkvh + ((size_t)nb * C3 + 2 * C + s * MID) * TV;  // V [m][k]
    const __half* Bg = g_atth + (size_t)bz * T * T;                        // att [q][t]
    uint32_t sb = (uint32_t)__cvta_generic_to_shared(sh);
    uint32_t A0 = sb, B0 = sb + 3 * ABH * 2;

    uint32_t aLO = ((lane & 15) * PA + (lane >> 4) * 8) * 2;
    uint32_t aF[4][2];
#pragma unroll
    for (int mi = 0; mi < 4; mi++)
#pragma unroll
        for (int ks = 0; ks < 2; ks++)
            aF[mi][ks] = aLO + ((mi * 16) * PA + ks * 16) * 2;
    uint32_t bLO = (((lane & 7) + ((lane >> 3) & 1) * 8) * PB + (lane >> 4) * 8) * 2;
    uint32_t bF[4][2];
#pragma unroll
    for (int j = 0; j < 4; j++)
#pragma unroll
        for (int ks = 0; ks < 2; ks++)
            bF[j][ks] = bLO + (wn + j * 16) * 2 + ks * 16 * PB * 2;

    float acc[4][8][4] = {};

    auto LOAD = [&](uint32_t aB, uint32_t bB, int kk) {
#pragma unroll
        for (int i = 0; i < 2; i++) {
            int e = tid + i * 128;
            int r = e >> 2, c = e & 3;
            cpa16s(aB + r * PA * 2 + c * 16, Ag + (size_t)(m0 + r) * T + kk + c * 8);
        }
#pragma unroll
        for (int i = 0; i < 8; i++) {
            int e = tid + i * 128;
            int r = e >> 5, c = e & 31;
            cpa16s(bB + r * PB * 2 + c * 16, Bg + (size_t)(kk + r) * T + c * 8);
        }
    };
    auto COMP = [&](uint32_t aB, uint32_t bB) {
#pragma unroll
        for (int ks = 0; ks < 2; ks++) {
            uint32_t a[4][4], b[8][2];
#pragma unroll
            for (int mi = 0; mi < 4; mi++)
                ldsm4(a[mi][0], a[mi][1], a[mi][2], a[mi][3], aB + aF[mi][ks]);
#pragma unroll
            for (int j = 0; j < 4; j++)
                ldsm4t(b[2 * j][0], b[2 * j][1], b[2 * j + 1][0], b[2 * j + 1][1], bB + bF[j][ks]);
#pragma unroll
            for (int mi = 0; mi < 4; mi++)
#pragma unroll
                for (int ni = 0; ni < 8; ni++) mma16(acc[mi][ni], a[mi], b[ni]);
        }
    };

    uint32_t aC = A0, aN = A0 + ABH * 2, aL = A0 + 2 * ABH * 2;
    uint32_t bC = B0, bN = B0 + BBH * 2, bL = B0 + 2 * BBH * 2;
    LOAD(aC, bC, 0); cpcommit();
    LOAD(aN, bN, 32); cpcommit();
    int kk = 64;
    const int NIT = 8;
#pragma unroll 1
    for (int it = 0; it < NIT; ++it) {
        cpwait<1>(); __syncthreads();
        if (it + 2 < NIT) { LOAD(aL, bL, kk); kk += 32; }
        COMP(aC, bC);
        cpcommit();
        ROT3(aC, aN, aL); ROT3(bC, bN, bL);
    }
    __syncthreads();
    // stage 64x256 fp16 tile (pitch 264), then scatter to y[ch][t][v]
    __half* St = sh;
#pragma unroll
    for (int mi = 0; mi < 4; mi++) {
        int r0 = mi * 16 + g;
#pragma unroll
        for (int ni = 0; ni < 8; ni++) {
            int col = wn + ni * 8 + 2 * tg;
            *(__half2*)&St[r0 * 264 + col] =
                __floats2half2_rn(acc[mi][ni][0], acc[mi][ni][1]);
            *(__half2*)&St[(r0 + 8) * 264 + col] =
                __floats2half2_rn(acc[mi][ni][2], acc[mi][ni][3]);
        }
    }
    __syncthreads();
    const int chbase = nb * C + s * MID;
#pragma unroll
    for (int it = 0; it < 128; ++it) {
        int e = tid + it * 128;
        int m = e & 63, t = e >> 6;
        int mg = m0 + m;
        int c = mg / 25, v = mg - c * 25;
        g_yh[((size_t)(chbase + c) * T + t) * V + v] = St[m * 264 + t];
    }
}

// ---------------------------------------------------------------------------
// FF + BN + residual + LeakyReLU. M=192 N=6400 K=192. Block 64x256, 4 warps.
// ---------------------------------------------------------------------------
__global__ __launch_bounds__(128) void k_ff(const float* __restrict__ x,
                                            const float* __restrict__ bias,
                                            const float* __restrict__ gamma,
                                            const float* __restrict__ beta,
                                            const float* __restrict__ mean,
                                            const float* __restrict__ var,
                                            float* __restrict__ out) {
    constexpr int PA = 40, PB = 264;
    constexpr int ABH = 64 * PA, BBH = 32 * PB;
    __shared__ __align__(16) __half sh[3 * (ABH + BBH)];
    const int bz = blockIdx.z, m0 = blockIdx.y * 64, n0 = blockIdx.x * 256;
    const int tid = threadIdx.x, lane = tid & 31, wid = tid >> 5;
    const int g = lane >> 2, tg = lane & 3;
    const int wn = wid * 64;
    const __half* Bg = g_yh + (size_t)bz * C * TV + n0;
    uint32_t sb = (uint32_t)__cvta_generic_to_shared(sh);
    uint32_t A0 = sb, B0 = sb + 3 * ABH * 2;

    uint32_t aLO = ((lane & 15) * PA + (lane >> 4) * 8) * 2;
    uint32_t aF[4][2];
#pragma unroll
    for (int mi = 0; mi < 4; mi++)
#pragma unroll
        for (int ks = 0; ks < 2; ks++)
            aF[mi][ks] = aLO + ((mi * 16) * PA + ks * 16) * 2;
    uint32_t bLO = (((lane & 7) + ((lane >> 3) & 1) * 8) * PB + (lane >> 4) * 8) * 2;
    uint32_t bF[4][2];
#pragma unroll
    for (int j = 0; j < 4; j++)
#pragma unroll
        for (int ks = 0; ks < 2; ks++)
            bF[j][ks] = bLO + (wn + j * 16) * 2 + ks * 16 * PB * 2;

    float acc[4][8][4] = {};

    auto LOAD = [&](uint32_t aB, uint32_t bB, int kk) {
#pragma unroll
        for (int i = 0; i < 2; i++) {
            int e = tid + i * 128;
            int r = e >> 2, c = e & 3;
            cpa16s(aB + r * PA * 2 + c * 16, g_wffh + (m0 + r) * C + kk + c * 8);
        }
#pragma unroll
        for (int i = 0; i < 8; i++) {
            int e = tid + i * 128;
            int r = e >> 5, c = e & 31;
            cpa16s(bB + r * PB * 2 + c * 16, Bg + (size_t)(kk + r) * TV + c * 8);
        }
    };
    auto COMP = [&](uint32_t aB, uint32_t bB) {
#pragma unroll
        for (int ks = 0; ks < 2; ks++) {
            uint32_t a[4][4], b[8][2];
#pragma unroll
            for (int mi = 0; mi < 4; mi++)
                ldsm4(a[mi][0], a[mi][1], a[mi][2], a[mi][3], aB + aF[mi][ks]);
#pragma unroll
            for (int j = 0; j < 4; j++)
                ldsm4t(b[2 * j][0], b[2 * j][1], b[2 * j + 1][0], b[2 * j + 1][1], bB + bF[j][ks]);
#pragma unroll
            for (int mi = 0; mi < 4; mi++)
#pragma unroll
                for (int ni = 0; ni < 8; ni++) mma16(acc[mi][ni], a[mi], b[ni]);
        }
    };

    uint32_t aC = A0, aN = A0 + ABH * 2, aL = A0 + 2 * ABH * 2;
    uint32_t bC = B0, bN = B0 + BBH * 2, bL = B0 + 2 * BBH * 2;
    LOAD(aC, bC, 0); cpcommit();
    LOAD(aN, bN, 32); cpcommit();
    int kk = 64;
    const int NIT = 6;
#pragma unroll 1
    for (int it = 0; it < NIT; ++it) {
        cpwait<1>(); __syncthreads();
        if (it + 2 < NIT) { LOAD(aL, bL, kk); kk += 32; }
        COMP(aC, bC);
        cpcommit();
        ROT3(aC, aN, aL); ROT3(bC, bN, bL);
    }
#pragma unroll
    for (int mi = 0; mi < 4; mi++) {
        int r0 = m0 + mi * 16 + g;
        int r1 = r0 + 8;
        float sc0 = gamma[r0] * rsqrtf(var[r0] + 1e-5f);
        float sh0 = beta[r0] - mean[r0] * sc0;
        float bb0 = bias[r0];
        float sc1 = gamma[r1] * rsqrtf(var[r1] + 1e-5f);
        float sh1 = beta[r1] - mean[r1] * sc1;
        float bb1 = bias[r1];
#pragma unroll
        for (int ni = 0; ni < 8; ni++) {
            int col = n0 + wn + ni * 8 + 2 * tg;
            size_t i0 = (size_t)(bz * C + r0) * TV + col;
            size_t i1 = (size_t)(bz * C + r1) * TV + col;
            float2 x0 = *(const float2*)&x[i0];
            float2 x1 = *(const float2*)&x[i1];
            float z, o0x, o0y, o1x, o1y;
            z = x0.x + (acc[mi][ni][0] + bb0) * sc0 + sh0; o0x = z >= 0.f ? z : 0.1f * z;
            z = x0.y + (acc[mi][ni][1] + bb0) * sc0 + sh0; o0y = z >= 0.f ? z : 0.1f * z;
            z = x1.x + (acc[mi][ni][2] + bb1) * sc1 + sh1; o1x = z >= 0.f ? z : 0.1f * z;
            z = x1.y + (acc[mi][ni][3] + bb1) * sc1 + sh1; o1y = z >= 0.f ? z : 0.1f * z;
            *(float2*)&out[i0] = make_float2(o0x, o0y);
            *(float2*)&out[i1] = make_float2(o1x, o1y);
        }
    }
}

extern "C" void kernel_launch(void* const* d_in, const int* in_sizes, int n_in,
                              void* d_out, int out_size) {
    const float* x     = (const float*)d_in[0];
    const float* w_in  = (const float*)d_in[1];
    const float* b_in  = (const float*)d_in[2];
    const float* w_ff  = (const float*)d_in[3];
    const float* b_ff  = (const float*)d_in[4];
    const float* gamma = (const float*)d_in[5];
    const float* beta  = (const float*)d_in[6];
    const float* mean  = (const float*)d_in[7];
    const float* var   = (const float*)d_in[8];
    float* out = (float*)d_out;

    k_prep<<<432, 256>>>(w_in, w_ff);
    k_tr <<<NBATCH * C, 256>>>(x);
    k_qkv<<<dim3(25, 9, 32), 128>>>(b_in);
    k_att<<<dim3(2, 2, 96), 128>>>();
    k_av <<<dim3(25, 96), 128>>>();
    k_ff <<<dim3(25, 3, 32), 128>>>(x, b_ff, gamma, beta, mean, var, out);
}